// round 2
// baseline (speedup 1.0000x reference)
#include <cuda_runtime.h>
#include <math.h>

#define BATCH 2
#define SEQ   2048
#define DIM   4096
#define NH    32
#define NKV   8
#define HD    128
#define MROWS 4096   // BATCH*SEQ
#define KVDIM 1024   // NKV*HD

// Scratch (zero-init .bss, no runtime allocation)
__device__ float g_q[(size_t)MROWS * DIM];     // 64 MB
__device__ float g_k[(size_t)MROWS * KVDIM];   // 16 MB
__device__ float g_v[(size_t)MROWS * KVDIM];   // 16 MB
__device__ float g_attn[(size_t)MROWS * DIM];  // 64 MB

// ---------------------------------------------------------------------------
// NT SGEMM: C[m,n] = sum_k A[m,k] * B[n,k]   (both row-major, K contiguous)
// 128x128 block tile, BK=16, 256 threads, 8x8 per-thread micro-tile.
// M,N multiples of 128; K multiple of 16 (true for all calls here).
// ---------------------------------------------------------------------------
__global__ void __launch_bounds__(256) sgemm_nt(
    const float* __restrict__ A, const float* __restrict__ Bm,
    float* __restrict__ C, int M, int N, int K)
{
    __shared__ float As[16][128];
    __shared__ float Bs[16][128];

    const int bm = blockIdx.y * 128;
    const int bn = blockIdx.x * 128;
    const int tid = threadIdx.x;
    const int tx = tid & 15;   // 0..15 -> n
    const int ty = tid >> 4;   // 0..15 -> m

    float acc[8][8];
#pragma unroll
    for (int i = 0; i < 8; i++)
#pragma unroll
        for (int j = 0; j < 8; j++) acc[i][j] = 0.0f;

    for (int k0 = 0; k0 < K; k0 += 16) {
        // Load 128x16 tiles of A and B (512 float4 each -> 2 per thread)
#pragma unroll
        for (int it = 0; it < 2; it++) {
            int i = tid + it * 256;
            int r  = i >> 2;          // 0..127
            int c4 = (i & 3) * 4;     // 0,4,8,12
            float4 va = *(const float4*)&A[(size_t)(bm + r) * K + k0 + c4];
            As[c4 + 0][r] = va.x; As[c4 + 1][r] = va.y;
            As[c4 + 2][r] = va.z; As[c4 + 3][r] = va.w;
            float4 vb = *(const float4*)&Bm[(size_t)(bn + r) * K + k0 + c4];
            Bs[c4 + 0][r] = vb.x; Bs[c4 + 1][r] = vb.y;
            Bs[c4 + 2][r] = vb.z; Bs[c4 + 3][r] = vb.w;
        }
        __syncthreads();

#pragma unroll
        for (int k = 0; k < 16; k++) {
            float ra[8], rb[8];
            *(float4*)&ra[0] = *(const float4*)&As[k][ty * 8];
            *(float4*)&ra[4] = *(const float4*)&As[k][ty * 8 + 4];
            *(float4*)&rb[0] = *(const float4*)&Bs[k][tx * 8];
            *(float4*)&rb[4] = *(const float4*)&Bs[k][tx * 8 + 4];
#pragma unroll
            for (int i = 0; i < 8; i++)
#pragma unroll
                for (int j = 0; j < 8; j++)
                    acc[i][j] += ra[i] * rb[j];
        }
        __syncthreads();
    }

#pragma unroll
    for (int i = 0; i < 8; i++) {
        size_t row = (size_t)(bm + ty * 8 + i) * N + bn + tx * 8;
        *(float4*)&C[row]     = *(float4*)&acc[i][0];
        *(float4*)&C[row + 4] = *(float4*)&acc[i][4];
    }
}

// ---------------------------------------------------------------------------
// RoPE: in-place on Q [MROWS, NH*HD] and K [MROWS, NKV*HD]
// pair i within head: (2i, 2i+1), freqs indexed by [s, i], i in 0..63
// ---------------------------------------------------------------------------
__global__ void rope_kernel(float* __restrict__ Q, float* __restrict__ K,
                            const float* __restrict__ fc, const float* __restrict__ fs)
{
    const int QP = MROWS * NH * 64;   // 8388608
    const int KP = MROWS * NKV * 64;  // 2097152
    int idx = blockIdx.x * blockDim.x + threadIdx.x;
    if (idx < QP) {
        int i = idx & 63;
        int h = (idx >> 6) & 31;
        int m = idx >> 11;
        int s = m & (SEQ - 1);
        float c  = fc[s * 64 + i];
        float sn = fs[s * 64 + i];
        float* p = Q + (size_t)m * DIM + h * HD + 2 * i;
        float xr = p[0], xi = p[1];
        p[0] = xr * c - xi * sn;
        p[1] = xr * sn + xi * c;
    } else if (idx < QP + KP) {
        int t = idx - QP;
        int i = t & 63;
        int h = (t >> 6) & 7;
        int m = t >> 9;
        int s = m & (SEQ - 1);
        float c  = fc[s * 64 + i];
        float sn = fs[s * 64 + i];
        float* p = K + (size_t)m * KVDIM + h * HD + 2 * i;
        float xr = p[0], xi = p[1];
        p[0] = xr * c - xi * sn;
        p[1] = xr * sn + xi * c;
    }
}

// ---------------------------------------------------------------------------
// Causal flash attention, fp32, 64-query x 64-key tiles, HD=128.
// grid: (SEQ/64, BATCH*NH), block: 256 threads (16x16), 4x4 S micro-tile,
// 4x8 O micro-tile. Dynamic smem: sQ 32K + sKV 32K + sP 16K = 80 KB.
// ---------------------------------------------------------------------------
__global__ void __launch_bounds__(256) attn_kernel(
    const float* __restrict__ Q, const float* __restrict__ Kc,
    const float* __restrict__ Vc, float* __restrict__ Oout)
{
    extern __shared__ float smem[];
    float* sQ  = smem;               // [64][128]
    float* sKV = smem + 64 * 128;    // [64][128]
    float* sP  = smem + 2 * 64 * 128;// [64][64]

    const int qi = blockIdx.x;          // query tile index 0..31
    const int bh = blockIdx.y;          // 0..63
    const int b  = bh >> 5;
    const int h  = bh & 31;
    const int kvh = h >> 2;             // n_rep = 4
    const int q0 = qi * 64;
    const int tid = threadIdx.x;
    const int tx = tid & 15;            // key/col dim
    const int ty = tid >> 4;            // query/row dim

    // Load Q tile [64,128]
    const size_t qbase = ((size_t)(b * SEQ + q0)) * DIM + h * HD;
#pragma unroll
    for (int it = 0; it < 8; it++) {
        int i = tid + it * 256;         // 0..2047
        int r = i >> 5;
        int c = (i & 31) * 4;
        *(float4*)&sQ[r * 128 + c] = *(const float4*)&Q[qbase + (size_t)r * DIM + c];
    }

    float m_i[4], l_i[4], Oa[4][8];
#pragma unroll
    for (int i = 0; i < 4; i++) { m_i[i] = -1e30f; l_i[i] = 0.0f; }
#pragma unroll
    for (int i = 0; i < 4; i++)
#pragma unroll
        for (int j = 0; j < 8; j++) Oa[i][j] = 0.0f;

    const size_t kbase = ((size_t)(b * SEQ)) * KVDIM + kvh * HD;
    const float scale = 0.08838834764831845f;  // 1/sqrt(128)

    for (int kt = 0; kt <= qi; kt++) {
        const int t0 = kt * 64;
        __syncthreads();  // protect sKV/sP from previous iteration's readers
        // Load K tile [64,128]
#pragma unroll
        for (int it = 0; it < 8; it++) {
            int i = tid + it * 256;
            int r = i >> 5;
            int c = (i & 31) * 4;
            *(float4*)&sKV[r * 128 + c] =
                *(const float4*)&Kc[kbase + (size_t)(t0 + r) * KVDIM + c];
        }
        __syncthreads();

        // S = Q K^T (4x4 micro-tile per thread)
        float sv[4][4];
#pragma unroll
        for (int i = 0; i < 4; i++)
#pragma unroll
            for (int j = 0; j < 4; j++) sv[i][j] = 0.0f;

#pragma unroll 8
        for (int d = 0; d < 128; d += 4) {
            float4 a0 = *(float4*)&sQ[(ty * 4 + 0) * 128 + d];
            float4 a1 = *(float4*)&sQ[(ty * 4 + 1) * 128 + d];
            float4 a2 = *(float4*)&sQ[(ty * 4 + 2) * 128 + d];
            float4 a3 = *(float4*)&sQ[(ty * 4 + 3) * 128 + d];
            float4 b0 = *(float4*)&sKV[(tx * 4 + 0) * 128 + d];
            float4 b1 = *(float4*)&sKV[(tx * 4 + 1) * 128 + d];
            float4 b2 = *(float4*)&sKV[(tx * 4 + 2) * 128 + d];
            float4 b3 = *(float4*)&sKV[(tx * 4 + 3) * 128 + d];
            float4 A[4] = {a0, a1, a2, a3};
            float4 Bv[4] = {b0, b1, b2, b3};
#pragma unroll
            for (int i = 0; i < 4; i++)
#pragma unroll
                for (int j = 0; j < 4; j++)
                    sv[i][j] += A[i].x * Bv[j].x + A[i].y * Bv[j].y +
                                A[i].z * Bv[j].z + A[i].w * Bv[j].w;
        }

        // scale + causal mask + row max
        float rowmax[4];
#pragma unroll
        for (int i = 0; i < 4; i++) {
            int srow = q0 + ty * 4 + i;
            float mx = -1e30f;
#pragma unroll
            for (int j = 0; j < 4; j++) {
                float s = sv[i][j] * scale;
                int t = t0 + tx * 4 + j;
                if (t > srow) s = -1e30f;
                sv[i][j] = s;
                mx = fmaxf(mx, s);
            }
            rowmax[i] = mx;
        }
#pragma unroll
        for (int off = 8; off > 0; off >>= 1)
#pragma unroll
            for (int i = 0; i < 4; i++)
                rowmax[i] = fmaxf(rowmax[i], __shfl_xor_sync(0xffffffffu, rowmax[i], off));

        float alpha[4], rowsum[4];
#pragma unroll
        for (int i = 0; i < 4; i++) {
            float mnew = fmaxf(m_i[i], rowmax[i]);
            alpha[i] = __expf(m_i[i] - mnew);
            m_i[i] = mnew;
            float rs = 0.0f;
#pragma unroll
            for (int j = 0; j < 4; j++) {
                sv[i][j] = __expf(sv[i][j] - mnew);
                rs += sv[i][j];
            }
            rowsum[i] = rs;
        }
#pragma unroll
        for (int off = 8; off > 0; off >>= 1)
#pragma unroll
            for (int i = 0; i < 4; i++)
                rowsum[i] += __shfl_xor_sync(0xffffffffu, rowsum[i], off);
#pragma unroll
        for (int i = 0; i < 4; i++) {
            l_i[i] = l_i[i] * alpha[i] + rowsum[i];
#pragma unroll
            for (int j = 0; j < 8; j++) Oa[i][j] *= alpha[i];
        }

        // store P tile to smem
#pragma unroll
        for (int i = 0; i < 4; i++)
#pragma unroll
            for (int j = 0; j < 4; j++)
                sP[(ty * 4 + i) * 64 + tx * 4 + j] = sv[i][j];
        __syncthreads();

        // Load V tile [64,128] into sKV (overwrite K; S already consumed)
#pragma unroll
        for (int it = 0; it < 8; it++) {
            int i = tid + it * 256;
            int r = i >> 5;
            int c = (i & 31) * 4;
            *(float4*)&sKV[r * 128 + c] =
                *(const float4*)&Vc[kbase + (size_t)(t0 + r) * KVDIM + c];
        }
        __syncthreads();

        // O += P @ V
#pragma unroll 4
        for (int t = 0; t < 64; t++) {
            float p0 = sP[(ty * 4 + 0) * 64 + t];
            float p1 = sP[(ty * 4 + 1) * 64 + t];
            float p2 = sP[(ty * 4 + 2) * 64 + t];
            float p3 = sP[(ty * 4 + 3) * 64 + t];
            float4 v0 = *(float4*)&sKV[t * 128 + tx * 8];
            float4 v1 = *(float4*)&sKV[t * 128 + tx * 8 + 4];
            Oa[0][0] += p0 * v0.x; Oa[0][1] += p0 * v0.y; Oa[0][2] += p0 * v0.z; Oa[0][3] += p0 * v0.w;
            Oa[0][4] += p0 * v1.x; Oa[0][5] += p0 * v1.y; Oa[0][6] += p0 * v1.z; Oa[0][7] += p0 * v1.w;
            Oa[1][0] += p1 * v0.x; Oa[1][1] += p1 * v0.y; Oa[1][2] += p1 * v0.z; Oa[1][3] += p1 * v0.w;
            Oa[1][4] += p1 * v1.x; Oa[1][5] += p1 * v1.y; Oa[1][6] += p1 * v1.z; Oa[1][7] += p1 * v1.w;
            Oa[2][0] += p2 * v0.x; Oa[2][1] += p2 * v0.y; Oa[2][2] += p2 * v0.z; Oa[2][3] += p2 * v0.w;
            Oa[2][4] += p2 * v1.x; Oa[2][5] += p2 * v1.y; Oa[2][6] += p2 * v1.z; Oa[2][7] += p2 * v1.w;
            Oa[3][0] += p3 * v0.x; Oa[3][1] += p3 * v0.y; Oa[3][2] += p3 * v0.z; Oa[3][3] += p3 * v0.w;
            Oa[3][4] += p3 * v1.x; Oa[3][5] += p3 * v1.y; Oa[3][6] += p3 * v1.z; Oa[3][7] += p3 * v1.w;
        }
    }

    // Normalize and write out [b, s, h*128 + d]
#pragma unroll
    for (int i = 0; i < 4; i++) {
        float inv = 1.0f / l_i[i];
        int srow = q0 + ty * 4 + i;
        float4 o0 = make_float4(Oa[i][0] * inv, Oa[i][1] * inv, Oa[i][2] * inv, Oa[i][3] * inv);
        float4 o1 = make_float4(Oa[i][4] * inv, Oa[i][5] * inv, Oa[i][6] * inv, Oa[i][7] * inv);
        size_t base = ((size_t)(b * SEQ + srow)) * DIM + h * HD + tx * 8;
        *(float4*)&Oout[base]     = o0;
        *(float4*)&Oout[base + 4] = o1;
    }
}

// ---------------------------------------------------------------------------
extern "C" void kernel_launch(void* const* d_in, const int* in_sizes, int n_in,
                              void* d_out, int out_size)
{
    const float* x  = (const float*)d_in[0];
    const float* wq = (const float*)d_in[1];
    const float* wk = (const float*)d_in[2];
    const float* wv = (const float*)d_in[3];
    const float* wo = (const float*)d_in[4];
    const float* fc = (const float*)d_in[5];
    const float* fs = (const float*)d_in[6];
    // d_in[7], d_in[8] = zero caches; d_in[9] = start_pos (0) — unused
    float* out = (float*)d_out;

    float *qp, *kp, *vp, *ap;
    cudaGetSymbolAddress((void**)&qp, g_q);
    cudaGetSymbolAddress((void**)&kp, g_k);
    cudaGetSymbolAddress((void**)&vp, g_v);
    cudaGetSymbolAddress((void**)&ap, g_attn);

    cudaFuncSetAttribute(attn_kernel, cudaFuncAttributeMaxDynamicSharedMemorySize, 81920);

    // QKV projections
    sgemm_nt<<<dim3(DIM / 128, MROWS / 128), 256>>>(x, wq, qp, MROWS, DIM, DIM);
    sgemm_nt<<<dim3(KVDIM / 128, MROWS / 128), 256>>>(x, wk, kp, MROWS, KVDIM, DIM);
    sgemm_nt<<<dim3(KVDIM / 128, MROWS / 128), 256>>>(x, wv, vp, MROWS, KVDIM, DIM);

    // RoPE on Q and K
    int total = MROWS * NH * 64 + MROWS * NKV * 64;
    rope_kernel<<<(total + 255) / 256, 256>>>(qp, kp, fc, fs);

    // Causal flash attention
    attn_kernel<<<dim3(SEQ / 64, BATCH * NH), 256, 81920>>>(qp, kp, vp, ap);

    // Output projection
    sgemm_nt<<<dim3(DIM / 128, MROWS / 128), 256>>>(ap, wo, out, MROWS, DIM, DIM);
}

// round 4
// speedup vs baseline: 1.5064x; 1.5064x over previous
#include <cuda_runtime.h>
#include <cuda_bf16.h>
#include <math.h>
#include <stdint.h>

#define BATCH 2
#define SEQ   2048
#define DIM   4096
#define NH    32
#define NKV   8
#define HD    128
#define MROWS 4096   // BATCH*SEQ
#define KVDIM 1024   // NKV*HD
#define K3    (3 * DIM)   // 12288: split-interleaved K

// ---------------- scratch (zero-init .bss, no runtime allocation) ----------
__device__ float g_q[(size_t)MROWS * DIM];
__device__ float g_k[(size_t)MROWS * KVDIM];
__device__ float g_v[(size_t)MROWS * KVDIM];
__device__ float g_attn[(size_t)MROWS * DIM];

__device__ uint16_t g_xs [(size_t)MROWS * K3];   // x split (A-side)
__device__ uint16_t g_as [(size_t)MROWS * K3];   // attn-out split (A-side)
__device__ uint16_t g_wqs[(size_t)DIM   * K3];   // weight splits (B-side)
__device__ uint16_t g_wks[(size_t)KVDIM * K3];
__device__ uint16_t g_wvs[(size_t)KVDIM * K3];
__device__ uint16_t g_wos[(size_t)DIM   * K3];

// ---------------- helpers ---------------------------------------------------
__device__ __forceinline__ uint32_t smem_u32(const void* p) {
    return (uint32_t)__cvta_generic_to_shared(p);
}
__device__ __forceinline__ void cp_async16(uint32_t dst, const void* src) {
    asm volatile("cp.async.cg.shared.global [%0], [%1], 16;" :: "r"(dst), "l"(src) : "memory");
}
__device__ __forceinline__ void cp_commit() {
    asm volatile("cp.async.commit_group;" ::: "memory");
}

#define LDSM_X4(r0, r1, r2, r3, addr) \
    asm volatile("ldmatrix.sync.aligned.m8n8.x4.shared.b16 {%0,%1,%2,%3}, [%4];" \
                 : "=r"(r0), "=r"(r1), "=r"(r2), "=r"(r3) : "r"(addr))

#define MMA_BF16(d, a, b0v, b1v) \
    asm volatile("mma.sync.aligned.m16n8k16.row.col.f32.bf16.bf16.f32 " \
                 "{%0,%1,%2,%3}, {%4,%5,%6,%7}, {%8,%9}, {%0,%1,%2,%3};" \
                 : "+f"((d)[0]), "+f"((d)[1]), "+f"((d)[2]), "+f"((d)[3]) \
                 : "r"((a)[0]), "r"((a)[1]), "r"((a)[2]), "r"((a)[3]), \
                   "r"(b0v), "r"(b1v))

// ---------------------------------------------------------------------------
// Split fp32 -> bf16 triplets. AMODE=1: (hi,lo,hi); AMODE=0: (hi,hi,lo).
// ---------------------------------------------------------------------------
template <int AMODE>
__global__ void split_kernel(const float* __restrict__ src, uint16_t* __restrict__ dst,
                             int total8)
{
    int t = blockIdx.x * blockDim.x + threadIdx.x;
    if (t >= total8) return;
    float4 v0 = *(const float4*)&src[(size_t)t * 8];
    float4 v1 = *(const float4*)&src[(size_t)t * 8 + 4];
    float f[8] = {v0.x, v0.y, v0.z, v0.w, v1.x, v1.y, v1.z, v1.w};
    __align__(16) uint16_t o[24];
#pragma unroll
    for (int j = 0; j < 8; j++) {
        __nv_bfloat16 hi = __float2bfloat16_rn(f[j]);
        __nv_bfloat16 lo = __float2bfloat16_rn(f[j] - __bfloat162float(hi));
        uint16_t hb = __bfloat16_as_ushort(hi);
        uint16_t lb = __bfloat16_as_ushort(lo);
        if (AMODE) { o[3*j] = hb; o[3*j+1] = lb; o[3*j+2] = hb; }
        else       { o[3*j] = hb; o[3*j+1] = hb; o[3*j+2] = lb; }
    }
    uint4* dp = (uint4*)&dst[(size_t)t * 24];
    dp[0] = *(uint4*)&o[0];
    dp[1] = *(uint4*)&o[8];
    dp[2] = *(uint4*)&o[16];
}

// ---------------------------------------------------------------------------
// HMMA bf16 GEMM: C[m,n] = sum_{k'} A[m,k'] * B[n,k'], K' = K3.
// 128x128 CTA tile, 8 warps (4x2), warp tile 32x64, mma.m16n8k16 bf16->fp32.
// 4-stage cp.async pipeline; K chunk = 32 bf16. Rows padded to 80B (odd
// multiple of 16B => conflict-free ldmatrix).
// ---------------------------------------------------------------------------
#define BKC         32
#define ROW_BYTES   80
#define STAGE_BYTES (256 * ROW_BYTES)     // A rows 0..127, B rows 128..255
#define NSTAGE      4
#define GSMEM       (NSTAGE * STAGE_BYTES)  // 81920
#define NITER       (K3 / BKC)            // 384

__global__ void __launch_bounds__(256) gemm_hmma(
    const uint16_t* __restrict__ A, const uint16_t* __restrict__ Bm,
    float* __restrict__ C, int M, int N)
{
    extern __shared__ __align__(1024) char smem[];
    const uint32_t sbase = smem_u32(smem);

    const int bm = blockIdx.y * 128;
    const int bn = blockIdx.x * 128;
    const int tid = threadIdx.x;
    const int wid = tid >> 5;
    const int lane = tid & 31;
    const int wm = wid & 3;     // M quadrant (32 rows)
    const int wn = wid >> 2;    // N half (64 cols)

    const uint16_t* ga0 = A  + (size_t)bm * K3;
    const uint16_t* gb0 = Bm + (size_t)bn * K3;

    // loader: thread -> (row group, 16B chunk); 4 rows-batches of 64
    const int lc = tid & 3;          // 16B chunk within 64B row
    const int lr = tid >> 2;         // 0..63

    auto load_stage = [&](int s, int chunk) {
        const uint32_t sa = sbase + (uint32_t)s * STAGE_BYTES;
        const size_t koff = (size_t)chunk * BKC + lc * 8;
#pragma unroll
        for (int j = 0; j < 4; j++) {
            int r = lr + j * 64;     // 0..255
            const uint16_t* src = (r < 128)
                ? ga0 + (size_t)r * K3 + koff
                : gb0 + (size_t)(r - 128) * K3 + koff;
            cp_async16(sa + (uint32_t)(r * ROW_BYTES + lc * 16), src);
        }
        cp_commit();
    };

    float d[2][8][4];
#pragma unroll
    for (int mi = 0; mi < 2; mi++)
#pragma unroll
        for (int nj = 0; nj < 8; nj++)
#pragma unroll
            for (int q = 0; q < 4; q++) d[mi][nj][q] = 0.0f;

    // ldmatrix per-lane address components
    const int grp  = lane >> 3;
    const int lrow = lane & 7;
    const int a_r = lrow + ((grp & 1) << 3);
    const int a_c = (grp >> 1) << 3;
    const int b_r = lrow + ((grp >> 1) << 3);
    const int b_c = (grp & 1) << 3;

    load_stage(0, 0);
    load_stage(1, 1);
    load_stage(2, 2);

    for (int i = 0; i < NITER; i++) {
        const int s = i & (NSTAGE - 1);
        asm volatile("cp.async.wait_group %0;" :: "n"(NSTAGE - 2) : "memory");
        __syncthreads();
        if (i + 3 < NITER) load_stage((i + 3) & (NSTAGE - 1), i + 3);
        else cp_commit();   // keep group accounting uniform

        const uint32_t aB = sbase + (uint32_t)s * STAGE_BYTES;
        const uint32_t bB = aB + 128 * ROW_BYTES;
#pragma unroll
        for (int step = 0; step < 2; step++) {
            uint32_t af[2][4];
#pragma unroll
            for (int mi = 0; mi < 2; mi++) {
                uint32_t addr = aB + (uint32_t)((wm * 32 + mi * 16 + a_r) * ROW_BYTES
                                                + (step * 16 + a_c) * 2);
                LDSM_X4(af[mi][0], af[mi][1], af[mi][2], af[mi][3], addr);
            }
#pragma unroll
            for (int njp = 0; njp < 4; njp++) {
                uint32_t b0, b1, b2, b3;
                uint32_t addr = bB + (uint32_t)((wn * 64 + njp * 16 + b_r) * ROW_BYTES
                                                + (step * 16 + b_c) * 2);
                LDSM_X4(b0, b1, b2, b3, addr);
#pragma unroll
                for (int mi = 0; mi < 2; mi++) {
                    MMA_BF16(d[mi][2 * njp],     af[mi], b0, b1);
                    MMA_BF16(d[mi][2 * njp + 1], af[mi], b2, b3);
                }
            }
        }
    }

    // Epilogue: direct fp32 stores
    const int er = lane >> 2;
    const int ec = (lane & 3) * 2;
#pragma unroll
    for (int mi = 0; mi < 2; mi++) {
#pragma unroll
        for (int nj = 0; nj < 8; nj++) {
            int r0 = bm + wm * 32 + mi * 16 + er;
            int c0 = bn + wn * 64 + nj * 8 + ec;
            *(float2*)&C[(size_t)r0 * N + c0]       = make_float2(d[mi][nj][0], d[mi][nj][1]);
            *(float2*)&C[(size_t)(r0 + 8) * N + c0] = make_float2(d[mi][nj][2], d[mi][nj][3]);
        }
    }
}

// ---------------------------------------------------------------------------
// RoPE (unchanged)
// ---------------------------------------------------------------------------
__global__ void rope_kernel(float* __restrict__ Q, float* __restrict__ K,
                            const float* __restrict__ fc, const float* __restrict__ fs)
{
    const int QP = MROWS * NH * 64;
    const int KP = MROWS * NKV * 64;
    int idx = blockIdx.x * blockDim.x + threadIdx.x;
    if (idx < QP) {
        int i = idx & 63;
        int h = (idx >> 6) & 31;
        int m = idx >> 11;
        int s = m & (SEQ - 1);
        float c  = fc[s * 64 + i];
        float sn = fs[s * 64 + i];
        float* p = Q + (size_t)m * DIM + h * HD + 2 * i;
        float xr = p[0], xi = p[1];
        p[0] = xr * c - xi * sn;
        p[1] = xr * sn + xi * c;
    } else if (idx < QP + KP) {
        int t = idx - QP;
        int i = t & 63;
        int h = (t >> 6) & 7;
        int m = t >> 9;
        int s = m & (SEQ - 1);
        float c  = fc[s * 64 + i];
        float sn = fs[s * 64 + i];
        float* p = K + (size_t)m * KVDIM + h * HD + 2 * i;
        float xr = p[0], xi = p[1];
        p[0] = xr * c - xi * sn;
        p[1] = xr * sn + xi * c;
    }
}

// ---------------------------------------------------------------------------
// Causal flash attention fp32 (unchanged from R2; proven correct)
// ---------------------------------------------------------------------------
__global__ void __launch_bounds__(256) attn_kernel(
    const float* __restrict__ Q, const float* __restrict__ Kc,
    const float* __restrict__ Vc, float* __restrict__ Oout)
{
    extern __shared__ float fsm[];
    float* sQ  = fsm;
    float* sKV = fsm + 64 * 128;
    float* sP  = fsm + 2 * 64 * 128;

    const int qi = blockIdx.x;
    const int bh = blockIdx.y;
    const int b  = bh >> 5;
    const int h  = bh & 31;
    const int kvh = h >> 2;
    const int q0 = qi * 64;
    const int tid = threadIdx.x;
    const int tx = tid & 15;
    const int ty = tid >> 4;

    const size_t qbase = ((size_t)(b * SEQ + q0)) * DIM + h * HD;
#pragma unroll
    for (int it = 0; it < 8; it++) {
        int i = tid + it * 256;
        int r = i >> 5;
        int c = (i & 31) * 4;
        *(float4*)&sQ[r * 128 + c] = *(const float4*)&Q[qbase + (size_t)r * DIM + c];
    }

    float m_i[4], l_i[4], Oa[4][8];
#pragma unroll
    for (int i = 0; i < 4; i++) { m_i[i] = -1e30f; l_i[i] = 0.0f; }
#pragma unroll
    for (int i = 0; i < 4; i++)
#pragma unroll
        for (int j = 0; j < 8; j++) Oa[i][j] = 0.0f;

    const size_t kbase = ((size_t)(b * SEQ)) * KVDIM + kvh * HD;
    const float scale = 0.08838834764831845f;

    for (int kt = 0; kt <= qi; kt++) {
        const int t0 = kt * 64;
        __syncthreads();
#pragma unroll
        for (int it = 0; it < 8; it++) {
            int i = tid + it * 256;
            int r = i >> 5;
            int c = (i & 31) * 4;
            *(float4*)&sKV[r * 128 + c] =
                *(const float4*)&Kc[kbase + (size_t)(t0 + r) * KVDIM + c];
        }
        __syncthreads();

        float sv[4][4];
#pragma unroll
        for (int i = 0; i < 4; i++)
#pragma unroll
            for (int j = 0; j < 4; j++) sv[i][j] = 0.0f;

#pragma unroll 8
        for (int dd = 0; dd < 128; dd += 4) {
            float4 A[4], Bv[4];
            A[0] = *(float4*)&sQ[(ty * 4 + 0) * 128 + dd];
            A[1] = *(float4*)&sQ[(ty * 4 + 1) * 128 + dd];
            A[2] = *(float4*)&sQ[(ty * 4 + 2) * 128 + dd];
            A[3] = *(float4*)&sQ[(ty * 4 + 3) * 128 + dd];
            Bv[0] = *(float4*)&sKV[(tx * 4 + 0) * 128 + dd];
            Bv[1] = *(float4*)&sKV[(tx * 4 + 1) * 128 + dd];
            Bv[2] = *(float4*)&sKV[(tx * 4 + 2) * 128 + dd];
            Bv[3] = *(float4*)&sKV[(tx * 4 + 3) * 128 + dd];
#pragma unroll
            for (int i = 0; i < 4; i++)
#pragma unroll
                for (int j = 0; j < 4; j++)
                    sv[i][j] += A[i].x * Bv[j].x + A[i].y * Bv[j].y +
                                A[i].z * Bv[j].z + A[i].w * Bv[j].w;
        }

        float rowmax[4];
#pragma unroll
        for (int i = 0; i < 4; i++) {
            int srow = q0 + ty * 4 + i;
            float mx = -1e30f;
#pragma unroll
            for (int j = 0; j < 4; j++) {
                float sc = sv[i][j] * scale;
                int t = t0 + tx * 4 + j;
                if (t > srow) sc = -1e30f;
                sv[i][j] = sc;
                mx = fmaxf(mx, sc);
            }
            rowmax[i] = mx;
        }
#pragma unroll
        for (int off = 8; off > 0; off >>= 1)
#pragma unroll
            for (int i = 0; i < 4; i++)
                rowmax[i] = fmaxf(rowmax[i], __shfl_xor_sync(0xffffffffu, rowmax[i], off));

        float alpha[4], rowsum[4];
#pragma unroll
        for (int i = 0; i < 4; i++) {
            float mnew = fmaxf(m_i[i], rowmax[i]);
            alpha[i] = __expf(m_i[i] - mnew);
            m_i[i] = mnew;
            float rs = 0.0f;
#pragma unroll
            for (int j = 0; j < 4; j++) {
                sv[i][j] = __expf(sv[i][j] - mnew);
                rs += sv[i][j];
            }
            rowsum[i] = rs;
        }
#pragma unroll
        for (int off = 8; off > 0; off >>= 1)
#pragma unroll
            for (int i = 0; i < 4; i++)
                rowsum[i] += __shfl_xor_sync(0xffffffffu, rowsum[i], off);
#pragma unroll
        for (int i = 0; i < 4; i++) {
            l_i[i] = l_i[i] * alpha[i] + rowsum[i];
#pragma unroll
            for (int j = 0; j < 8; j++) Oa[i][j] *= alpha[i];
        }

#pragma unroll
        for (int i = 0; i < 4; i++)
#pragma unroll
            for (int j = 0; j < 4; j++)
                sP[(ty * 4 + i) * 64 + tx * 4 + j] = sv[i][j];
        __syncthreads();

#pragma unroll
        for (int it = 0; it < 8; it++) {
            int i = tid + it * 256;
            int r = i >> 5;
            int c = (i & 31) * 4;
            *(float4*)&sKV[r * 128 + c] =
                *(const float4*)&Vc[kbase + (size_t)(t0 + r) * KVDIM + c];
        }
        __syncthreads();

#pragma unroll 4
        for (int t = 0; t < 64; t++) {
            float p0 = sP[(ty * 4 + 0) * 64 + t];
            float p1 = sP[(ty * 4 + 1) * 64 + t];
            float p2 = sP[(ty * 4 + 2) * 64 + t];
            float p3 = sP[(ty * 4 + 3) * 64 + t];
            float4 v0 = *(float4*)&sKV[t * 128 + tx * 8];
            float4 v1 = *(float4*)&sKV[t * 128 + tx * 8 + 4];
            Oa[0][0] += p0 * v0.x; Oa[0][1] += p0 * v0.y; Oa[0][2] += p0 * v0.z; Oa[0][3] += p0 * v0.w;
            Oa[0][4] += p0 * v1.x; Oa[0][5] += p0 * v1.y; Oa[0][6] += p0 * v1.z; Oa[0][7] += p0 * v1.w;
            Oa[1][0] += p1 * v0.x; Oa[1][1] += p1 * v0.y; Oa[1][2] += p1 * v0.z; Oa[1][3] += p1 * v0.w;
            Oa[1][4] += p1 * v1.x; Oa[1][5] += p1 * v1.y; Oa[1][6] += p1 * v1.z; Oa[1][7] += p1 * v1.w;
            Oa[2][0] += p2 * v0.x; Oa[2][1] += p2 * v0.y; Oa[2][2] += p2 * v0.z; Oa[2][3] += p2 * v0.w;
            Oa[2][4] += p2 * v1.x; Oa[2][5] += p2 * v1.y; Oa[2][6] += p2 * v1.z; Oa[2][7] += p2 * v1.w;
            Oa[3][0] += p3 * v0.x; Oa[3][1] += p3 * v0.y; Oa[3][2] += p3 * v0.z; Oa[3][3] += p3 * v0.w;
            Oa[3][4] += p3 * v1.x; Oa[3][5] += p3 * v1.y; Oa[3][6] += p3 * v1.z; Oa[3][7] += p3 * v1.w;
        }
    }

#pragma unroll
    for (int i = 0; i < 4; i++) {
        float inv = 1.0f / l_i[i];
        int srow = q0 + ty * 4 + i;
        float4 o0 = make_float4(Oa[i][0] * inv, Oa[i][1] * inv, Oa[i][2] * inv, Oa[i][3] * inv);
        float4 o1 = make_float4(Oa[i][4] * inv, Oa[i][5] * inv, Oa[i][6] * inv, Oa[i][7] * inv);
        size_t base = ((size_t)(b * SEQ + srow)) * DIM + h * HD + tx * 8;
        *(float4*)&Oout[base]     = o0;
        *(float4*)&Oout[base + 4] = o1;
    }
}

// ---------------------------------------------------------------------------
extern "C" void kernel_launch(void* const* d_in, const int* in_sizes, int n_in,
                              void* d_out, int out_size)
{
    const float* x  = (const float*)d_in[0];
    const float* wq = (const float*)d_in[1];
    const float* wk = (const float*)d_in[2];
    const float* wv = (const float*)d_in[3];
    const float* wo = (const float*)d_in[4];
    const float* fc = (const float*)d_in[5];
    const float* fs = (const float*)d_in[6];
    float* out = (float*)d_out;

    float *qp, *kp, *vp, *ap;
    uint16_t *xs, *as, *wqs, *wks, *wvs, *wos;
    cudaGetSymbolAddress((void**)&qp, g_q);
    cudaGetSymbolAddress((void**)&kp, g_k);
    cudaGetSymbolAddress((void**)&vp, g_v);
    cudaGetSymbolAddress((void**)&ap, g_attn);
    cudaGetSymbolAddress((void**)&xs, g_xs);
    cudaGetSymbolAddress((void**)&as, g_as);
    cudaGetSymbolAddress((void**)&wqs, g_wqs);
    cudaGetSymbolAddress((void**)&wks, g_wks);
    cudaGetSymbolAddress((void**)&wvs, g_wvs);
    cudaGetSymbolAddress((void**)&wos, g_wos);

    cudaFuncSetAttribute(attn_kernel, cudaFuncAttributeMaxDynamicSharedMemorySize, 81920);
    cudaFuncSetAttribute(gemm_hmma, cudaFuncAttributeMaxDynamicSharedMemorySize, GSMEM);

    // Split operands into bf16 triplets
    {
        int t8_big = MROWS * DIM / 8;
        int t8_kv  = KVDIM * DIM / 8;
        split_kernel<1><<<t8_big / 256, 256>>>(x,  xs,  t8_big);
        split_kernel<0><<<t8_big / 256, 256>>>(wq, wqs, t8_big);
        split_kernel<0><<<t8_kv  / 256, 256>>>(wk, wks, t8_kv);
        split_kernel<0><<<t8_kv  / 256, 256>>>(wv, wvs, t8_kv);
        split_kernel<0><<<t8_big / 256, 256>>>(wo, wos, t8_big);
    }

    // QKV projections on tensor cores (HMMA)
    gemm_hmma<<<dim3(DIM   / 128, MROWS / 128), 256, GSMEM>>>(xs, wqs, qp, MROWS, DIM);
    gemm_hmma<<<dim3(KVDIM / 128, MROWS / 128), 256, GSMEM>>>(xs, wks, kp, MROWS, KVDIM);
    gemm_hmma<<<dim3(KVDIM / 128, MROWS / 128), 256, GSMEM>>>(xs, wvs, vp, MROWS, KVDIM);

    // RoPE
    int total = MROWS * NH * 64 + MROWS * NKV * 64;
    rope_kernel<<<(total + 255) / 256, 256>>>(qp, kp, fc, fs);

    // Attention (fp32)
    attn_kernel<<<dim3(SEQ / 64, BATCH * NH), 256, 81920>>>(qp, kp, vp, ap);

    // Split attention output, project
    split_kernel<1><<<(MROWS * DIM / 8) / 256, 256>>>(ap, as, MROWS * DIM / 8);
    gemm_hmma<<<dim3(DIM / 128, MROWS / 128), 256, GSMEM>>>(as, wos, out, MROWS, DIM);
}

// round 5
// speedup vs baseline: 3.0852x; 2.0481x over previous
#include <cuda_runtime.h>
#include <cuda_bf16.h>
#include <math.h>
#include <stdint.h>

#define BATCH 2
#define SEQ   2048
#define DIM   4096
#define NH    32
#define NKV   8
#define HD    128
#define MROWS 4096   // BATCH*SEQ
#define KVDIM 1024   // NKV*HD
#define K3    (3 * DIM)   // 12288: split-interleaved K

// ---------------- scratch (zero-init .bss, no runtime allocation) ----------
__device__ float g_q[(size_t)MROWS * DIM];
__device__ float g_k[(size_t)MROWS * KVDIM];
__device__ float g_v[(size_t)MROWS * KVDIM];
__device__ float g_attn[(size_t)MROWS * DIM];

__device__ uint16_t g_xs [(size_t)MROWS * K3];   // x split (A-side)
__device__ uint16_t g_as [(size_t)MROWS * K3];   // attn-out split (A-side)
__device__ uint16_t g_wqs[(size_t)DIM   * K3];   // weight splits (B-side)
__device__ uint16_t g_wks[(size_t)KVDIM * K3];
__device__ uint16_t g_wvs[(size_t)KVDIM * K3];
__device__ uint16_t g_wos[(size_t)DIM   * K3];

// attention split operands
__device__ uint16_t g_qs2[(size_t)BATCH * NH  * SEQ * 384];   // Q': rope+scale, (hi,lo,hi)
__device__ uint16_t g_ks2[(size_t)BATCH * NKV * SEQ * 384];   // K': rope, (hi,hi,lo)
__device__ uint16_t g_vs2[(size_t)BATCH * NKV * (3*SEQ) * HD]; // V': rows 3t,3t+1=hi, 3t+2=lo

// ---------------- helpers ---------------------------------------------------
__device__ __forceinline__ uint32_t smem_u32(const void* p) {
    return (uint32_t)__cvta_generic_to_shared(p);
}
__device__ __forceinline__ void cp_async16(uint32_t dst, const void* src) {
    asm volatile("cp.async.cg.shared.global [%0], [%1], 16;" :: "r"(dst), "l"(src) : "memory");
}
__device__ __forceinline__ void cp_commit() {
    asm volatile("cp.async.commit_group;" ::: "memory");
}

#define LDSM_X4(r0, r1, r2, r3, addr) \
    asm volatile("ldmatrix.sync.aligned.m8n8.x4.shared.b16 {%0,%1,%2,%3}, [%4];" \
                 : "=r"(r0), "=r"(r1), "=r"(r2), "=r"(r3) : "r"(addr))

#define LDSM_X4_T(r0, r1, r2, r3, addr) \
    asm volatile("ldmatrix.sync.aligned.m8n8.x4.trans.shared.b16 {%0,%1,%2,%3}, [%4];" \
                 : "=r"(r0), "=r"(r1), "=r"(r2), "=r"(r3) : "r"(addr))

#define MMA_BF16(d, a, b0v, b1v) \
    asm volatile("mma.sync.aligned.m16n8k16.row.col.f32.bf16.bf16.f32 " \
                 "{%0,%1,%2,%3}, {%4,%5,%6,%7}, {%8,%9}, {%0,%1,%2,%3};" \
                 : "+f"((d)[0]), "+f"((d)[1]), "+f"((d)[2]), "+f"((d)[3]) \
                 : "r"((a)[0]), "r"((a)[1]), "r"((a)[2]), "r"((a)[3]), \
                   "r"(b0v), "r"(b1v))

// ---------------------------------------------------------------------------
// Split fp32 -> bf16 triplets. AMODE=1: (hi,lo,hi); AMODE=0: (hi,hi,lo).
// ---------------------------------------------------------------------------
template <int AMODE>
__global__ void split_kernel(const float* __restrict__ src, uint16_t* __restrict__ dst,
                             int total8)
{
    int t = blockIdx.x * blockDim.x + threadIdx.x;
    if (t >= total8) return;
    float4 v0 = *(const float4*)&src[(size_t)t * 8];
    float4 v1 = *(const float4*)&src[(size_t)t * 8 + 4];
    float f[8] = {v0.x, v0.y, v0.z, v0.w, v1.x, v1.y, v1.z, v1.w};
    __align__(16) uint16_t o[24];
#pragma unroll
    for (int j = 0; j < 8; j++) {
        __nv_bfloat16 hi = __float2bfloat16_rn(f[j]);
        __nv_bfloat16 lo = __float2bfloat16_rn(f[j] - __bfloat162float(hi));
        uint16_t hb = __bfloat16_as_ushort(hi);
        uint16_t lb = __bfloat16_as_ushort(lo);
        if (AMODE) { o[3*j] = hb; o[3*j+1] = lb; o[3*j+2] = hb; }
        else       { o[3*j] = hb; o[3*j+1] = hb; o[3*j+2] = lb; }
    }
    uint4* dp = (uint4*)&dst[(size_t)t * 24];
    dp[0] = *(uint4*)&o[0];
    dp[1] = *(uint4*)&o[8];
    dp[2] = *(uint4*)&o[16];
}

// ---------------------------------------------------------------------------
// HMMA bf16 GEMM (unchanged from R4; proven)
// ---------------------------------------------------------------------------
#define BKC         32
#define ROW_BYTES   80
#define STAGE_BYTES (256 * ROW_BYTES)
#define NSTAGE      4
#define GSMEM       (NSTAGE * STAGE_BYTES)
#define NITER       (K3 / BKC)

__global__ void __launch_bounds__(256) gemm_hmma(
    const uint16_t* __restrict__ A, const uint16_t* __restrict__ Bm,
    float* __restrict__ C, int M, int N)
{
    extern __shared__ __align__(1024) char smem[];
    const uint32_t sbase = smem_u32(smem);

    const int bm = blockIdx.y * 128;
    const int bn = blockIdx.x * 128;
    const int tid = threadIdx.x;
    const int wid = tid >> 5;
    const int lane = tid & 31;
    const int wm = wid & 3;
    const int wn = wid >> 2;

    const uint16_t* ga0 = A  + (size_t)bm * K3;
    const uint16_t* gb0 = Bm + (size_t)bn * K3;

    const int lc = tid & 3;
    const int lr = tid >> 2;

    auto load_stage = [&](int s, int chunk) {
        const uint32_t sa = sbase + (uint32_t)s * STAGE_BYTES;
        const size_t koff = (size_t)chunk * BKC + lc * 8;
#pragma unroll
        for (int j = 0; j < 4; j++) {
            int r = lr + j * 64;
            const uint16_t* src = (r < 128)
                ? ga0 + (size_t)r * K3 + koff
                : gb0 + (size_t)(r - 128) * K3 + koff;
            cp_async16(sa + (uint32_t)(r * ROW_BYTES + lc * 16), src);
        }
        cp_commit();
    };

    float d[2][8][4];
#pragma unroll
    for (int mi = 0; mi < 2; mi++)
#pragma unroll
        for (int nj = 0; nj < 8; nj++)
#pragma unroll
            for (int q = 0; q < 4; q++) d[mi][nj][q] = 0.0f;

    const int grp  = lane >> 3;
    const int lrow = lane & 7;
    const int a_r = lrow + ((grp & 1) << 3);
    const int a_c = (grp >> 1) << 3;
    const int b_r = lrow + ((grp >> 1) << 3);
    const int b_c = (grp & 1) << 3;

    load_stage(0, 0);
    load_stage(1, 1);
    load_stage(2, 2);

    for (int i = 0; i < NITER; i++) {
        const int s = i & (NSTAGE - 1);
        asm volatile("cp.async.wait_group %0;" :: "n"(NSTAGE - 2) : "memory");
        __syncthreads();
        if (i + 3 < NITER) load_stage((i + 3) & (NSTAGE - 1), i + 3);
        else cp_commit();

        const uint32_t aB = sbase + (uint32_t)s * STAGE_BYTES;
        const uint32_t bB = aB + 128 * ROW_BYTES;
#pragma unroll
        for (int step = 0; step < 2; step++) {
            uint32_t af[2][4];
#pragma unroll
            for (int mi = 0; mi < 2; mi++) {
                uint32_t addr = aB + (uint32_t)((wm * 32 + mi * 16 + a_r) * ROW_BYTES
                                                + (step * 16 + a_c) * 2);
                LDSM_X4(af[mi][0], af[mi][1], af[mi][2], af[mi][3], addr);
            }
#pragma unroll
            for (int njp = 0; njp < 4; njp++) {
                uint32_t b0, b1, b2, b3;
                uint32_t addr = bB + (uint32_t)((wn * 64 + njp * 16 + b_r) * ROW_BYTES
                                                + (step * 16 + b_c) * 2);
                LDSM_X4(b0, b1, b2, b3, addr);
#pragma unroll
                for (int mi = 0; mi < 2; mi++) {
                    MMA_BF16(d[mi][2 * njp],     af[mi], b0, b1);
                    MMA_BF16(d[mi][2 * njp + 1], af[mi], b2, b3);
                }
            }
        }
    }

    const int er = lane >> 2;
    const int ec = (lane & 3) * 2;
#pragma unroll
    for (int mi = 0; mi < 2; mi++) {
#pragma unroll
        for (int nj = 0; nj < 8; nj++) {
            int r0 = bm + wm * 32 + mi * 16 + er;
            int c0 = bn + wn * 64 + nj * 8 + ec;
            *(float2*)&C[(size_t)r0 * N + c0]       = make_float2(d[mi][nj][0], d[mi][nj][1]);
            *(float2*)&C[(size_t)(r0 + 8) * N + c0] = make_float2(d[mi][nj][2], d[mi][nj][3]);
        }
    }
}

// ---------------------------------------------------------------------------
// RoPE + split for Q (A-side triplets, folds 1/sqrt(HD) scale) and K (B-side).
// One thread = 4 rope pairs (8 contiguous dims) of one row.
// ---------------------------------------------------------------------------
template <int ISQ>
__global__ void rope_split(const float* __restrict__ src, uint16_t* __restrict__ dst,
                           const float* __restrict__ fc, const float* __restrict__ fs)
{
    const int HEADS = ISQ ? NH : NKV;
    int gid = blockIdx.x * blockDim.x + threadIdx.x;
    int part = gid & 15;
    int row  = gid >> 4;                 // (b*HEADS + h)*SEQ + s
    int s = row & (SEQ - 1);
    int bh = row >> 11;                  // b*HEADS + h
    int h = bh % HEADS;
    int b = bh / HEADS;
    const float scale = ISQ ? 0.08838834764831845f : 1.0f;

    const float* in = src + ((size_t)(b * SEQ + s)) * (HEADS * HD) + h * HD + part * 8;
    float vals[8];
    *(float4*)&vals[0] = *(const float4*)&in[0];
    *(float4*)&vals[4] = *(const float4*)&in[4];

    __align__(16) uint16_t o[24];
#pragma unroll
    for (int p = 0; p < 4; p++) {
        int i = part * 4 + p;            // rope pair index 0..63
        float c  = fc[s * 64 + i];
        float sn = fs[s * 64 + i];
        float xr = vals[2 * p], xi = vals[2 * p + 1];
        float rr = (xr * c - xi * sn) * scale;
        float ri = (xr * sn + xi * c) * scale;
        float f2[2] = {rr, ri};
#pragma unroll
        for (int e = 0; e < 2; e++) {
            __nv_bfloat16 hi = __float2bfloat16_rn(f2[e]);
            __nv_bfloat16 lo = __float2bfloat16_rn(f2[e] - __bfloat162float(hi));
            uint16_t hb = __bfloat16_as_ushort(hi);
            uint16_t lb = __bfloat16_as_ushort(lo);
            int j = p * 2 + e;           // local dim 0..7
            if (ISQ) { o[3*j] = hb; o[3*j+1] = lb; o[3*j+2] = hb; }
            else     { o[3*j] = hb; o[3*j+1] = hb; o[3*j+2] = lb; }
        }
    }
    uint4* dp = (uint4*)(dst + (size_t)row * 384 + part * 24);
    dp[0] = *(uint4*)&o[0];
    dp[1] = *(uint4*)&o[8];
    dp[2] = *(uint4*)&o[16];
}

// ---------------------------------------------------------------------------
// V split: rows 3t,3t+1 = hi, 3t+2 = lo. One thread = 8 dims of one (b,kv,t).
// ---------------------------------------------------------------------------
__global__ void split_v_kernel(const float* __restrict__ src, uint16_t* __restrict__ dst)
{
    int gid = blockIdx.x * blockDim.x + threadIdx.x;
    int part = gid & 15;
    int row  = gid >> 4;                 // (b*NKV + kv)*SEQ + t
    int t = row & (SEQ - 1);
    int bkv = row >> 11;
    int kv = bkv & (NKV - 1);
    int b = bkv >> 3;

    const float* in = src + ((size_t)(b * SEQ + t)) * KVDIM + kv * HD + part * 8;
    float vals[8];
    *(float4*)&vals[0] = *(const float4*)&in[0];
    *(float4*)&vals[4] = *(const float4*)&in[4];

    __align__(16) uint16_t hi8[8], lo8[8];
#pragma unroll
    for (int j = 0; j < 8; j++) {
        __nv_bfloat16 hi = __float2bfloat16_rn(vals[j]);
        __nv_bfloat16 lo = __float2bfloat16_rn(vals[j] - __bfloat162float(hi));
        hi8[j] = __bfloat16_as_ushort(hi);
        lo8[j] = __bfloat16_as_ushort(lo);
    }
    uint16_t* out = dst + ((size_t)bkv * (3 * SEQ) + 3 * t) * HD + part * 8;
    *(uint4*)&out[0]        = *(uint4*)&hi8[0];
    *(uint4*)&out[HD]       = *(uint4*)&hi8[0];
    *(uint4*)&out[2 * HD]   = *(uint4*)&lo8[0];
}

// ---------------------------------------------------------------------------
// HMMA causal flash attention with 3-term bf16 split.
// CTA = 64 q rows x (qi+1) 64-t tiles. 8 warps: wm=wid&3 (16 rows), wn=wid>>2
// (t-half). Independent online softmax per t-half; merged at the end.
// ---------------------------------------------------------------------------
#define SQ_STR   784
#define SK_STR   784
#define SV_STR   272
#define SP_STR   400
#define SQ_OFF   0
#define SK_OFF   50176
#define SV_OFF   100352
#define SP_OFF   152576
#define ATT_SMEM 178176

__global__ void __launch_bounds__(256) attn_mma(
    const uint16_t* __restrict__ Qs, const uint16_t* __restrict__ Ks,
    const uint16_t* __restrict__ Vs, float* __restrict__ Oout)
{
    extern __shared__ __align__(1024) char smem[];
    const uint32_t sQ = smem_u32(smem) + SQ_OFF;
    const uint32_t sK = smem_u32(smem) + SK_OFF;
    const uint32_t sV = smem_u32(smem) + SV_OFF;
    const uint32_t sP = smem_u32(smem) + SP_OFF;
    float* mergeO = (float*)smem;                     // reuse sQ region at end
    float* mergeM = (float*)(smem + 32768);
    float* mergeL = (float*)(smem + 32768 + 256);

    const int qi = (SEQ / 64 - 1) - blockIdx.x;       // big tiles first
    const int bh = blockIdx.y;
    const int b = bh >> 5, h = bh & 31, kvh = h >> 2;
    const int q0 = qi * 64;
    const int tid = threadIdx.x;
    const int wid = tid >> 5, lane = tid & 31;
    const int wm = wid & 3, wn = wid >> 2;
    const int grp = lane >> 3, lrow = lane & 7;

    // load Q' tile [64 x 384]
    const uint16_t* gq = Qs + ((size_t)(b * NH + h) * SEQ + q0) * 384;
#pragma unroll
    for (int j = 0; j < 12; j++) {
        int id = tid + j * 256;
        int r = id / 48, c = id % 48;
        cp_async16(sQ + (uint32_t)(r * SQ_STR + c * 16), gq + (size_t)r * 384 + c * 8);
    }
    cp_commit();

    float m0 = -1e30f, m1 = -1e30f, l0 = 0.0f, l1 = 0.0f;
    float Oc[16][4];
#pragma unroll
    for (int j = 0; j < 16; j++)
#pragma unroll
        for (int q = 0; q < 4; q++) Oc[j][q] = 0.0f;

    const uint16_t* gk = Ks + ((size_t)(b * NKV + kvh) * SEQ) * 384;
    const uint16_t* gv = Vs + ((size_t)(b * NKV + kvh) * (3 * SEQ)) * HD;

    const int ra = wm * 16 + (lane >> 2);   // local row for vals 0,1; +8 for 2,3

    for (int kt = 0; kt <= qi; kt++) {
        const int t0 = kt * 64;
        __syncthreads();   // all warps done reading sK/sV from prev tile
#pragma unroll
        for (int j = 0; j < 12; j++) {
            int id = tid + j * 256;
            int r = id / 48, c = id % 48;
            cp_async16(sK + (uint32_t)(r * SK_STR + c * 16),
                       gk + ((size_t)(t0 + r)) * 384 + c * 8);
        }
#pragma unroll
        for (int j = 0; j < 12; j++) {
            int id = tid + j * 256;
            int r = id / 16, c = id % 16;
            cp_async16(sV + (uint32_t)(r * SV_STR + c * 16),
                       gv + ((size_t)(t0 * 3 + r)) * HD + c * 8);
        }
        cp_commit();
        asm volatile("cp.async.wait_group 0;" ::: "memory");
        __syncthreads();

        // ---- S = Q' K'^T  (k = 384) ----
        float Sa[4][4];
#pragma unroll
        for (int nt = 0; nt < 4; nt++)
#pragma unroll
            for (int q = 0; q < 4; q++) Sa[nt][q] = 0.0f;

#pragma unroll
        for (int ks = 0; ks < 24; ks++) {
            uint32_t A[4];
            uint32_t aaddr = sQ + (uint32_t)((wm * 16 + lrow + ((grp & 1) << 3)) * SQ_STR
                                             + (ks * 16 + ((grp >> 1) << 3)) * 2);
            LDSM_X4(A[0], A[1], A[2], A[3], aaddr);
#pragma unroll
            for (int ntp = 0; ntp < 2; ntp++) {
                uint32_t b0, b1, b2, b3;
                uint32_t baddr = sK + (uint32_t)((wn * 32 + ntp * 16 + lrow + ((grp >> 1) << 3)) * SK_STR
                                                 + (ks * 16 + ((grp & 1) << 3)) * 2);
                LDSM_X4(b0, b1, b2, b3, baddr);
                MMA_BF16(Sa[2 * ntp],     A, b0, b1);
                MMA_BF16(Sa[2 * ntp + 1], A, b2, b3);
            }
        }

        // ---- causal mask (diag tile only; t0 == q0 there) ----
        if (kt == qi) {
#pragma unroll
            for (int nt = 0; nt < 4; nt++) {
                int tb = wn * 32 + nt * 8 + 2 * (lane & 3);
                if (tb     > ra)     Sa[nt][0] = -1e30f;
                if (tb + 1 > ra)     Sa[nt][1] = -1e30f;
                if (tb     > ra + 8) Sa[nt][2] = -1e30f;
                if (tb + 1 > ra + 8) Sa[nt][3] = -1e30f;
            }
        }

        // ---- online softmax (per t-half) ----
        float hm0 = -1e30f, hm1 = -1e30f;
#pragma unroll
        for (int nt = 0; nt < 4; nt++) {
            hm0 = fmaxf(hm0, fmaxf(Sa[nt][0], Sa[nt][1]));
            hm1 = fmaxf(hm1, fmaxf(Sa[nt][2], Sa[nt][3]));
        }
        hm0 = fmaxf(hm0, __shfl_xor_sync(0xffffffffu, hm0, 1));
        hm0 = fmaxf(hm0, __shfl_xor_sync(0xffffffffu, hm0, 2));
        hm1 = fmaxf(hm1, __shfl_xor_sync(0xffffffffu, hm1, 1));
        hm1 = fmaxf(hm1, __shfl_xor_sync(0xffffffffu, hm1, 2));

        float mn0 = fmaxf(m0, hm0), mn1 = fmaxf(m1, hm1);
        float al0 = __expf(m0 - mn0), al1 = __expf(m1 - mn1);
        m0 = mn0; m1 = mn1;

        float hs0 = 0.0f, hs1 = 0.0f;
#pragma unroll
        for (int nt = 0; nt < 4; nt++) {
            Sa[nt][0] = __expf(Sa[nt][0] - mn0); hs0 += Sa[nt][0];
            Sa[nt][1] = __expf(Sa[nt][1] - mn0); hs0 += Sa[nt][1];
            Sa[nt][2] = __expf(Sa[nt][2] - mn1); hs1 += Sa[nt][2];
            Sa[nt][3] = __expf(Sa[nt][3] - mn1); hs1 += Sa[nt][3];
        }
        hs0 += __shfl_xor_sync(0xffffffffu, hs0, 1);
        hs0 += __shfl_xor_sync(0xffffffffu, hs0, 2);
        hs1 += __shfl_xor_sync(0xffffffffu, hs1, 1);
        hs1 += __shfl_xor_sync(0xffffffffu, hs1, 2);
        l0 = l0 * al0 + hs0;
        l1 = l1 * al1 + hs1;
#pragma unroll
        for (int j = 0; j < 16; j++) {
            Oc[j][0] *= al0; Oc[j][1] *= al0;
            Oc[j][2] *= al1; Oc[j][3] *= al1;
        }

        // ---- write P' split triplets to smem [row][3t..3t+2] ----
        __syncwarp();
#pragma unroll
        for (int nt = 0; nt < 4; nt++) {
            int tl0 = wn * 32 + nt * 8 + 2 * (lane & 3);
#pragma unroll
            for (int q = 0; q < 4; q++) {
                int row = ra + ((q >> 1) << 3);
                int t = tl0 + (q & 1);
                float p = Sa[nt][q];
                __nv_bfloat16 hi = __float2bfloat16_rn(p);
                __nv_bfloat16 lo = __float2bfloat16_rn(p - __bfloat162float(hi));
                uint16_t hb = __bfloat16_as_ushort(hi);
                uint16_t lb = __bfloat16_as_ushort(lo);
                uint32_t ad = sP + (uint32_t)(row * SP_STR + t * 6);
                asm volatile("st.shared.u16 [%0], %1;" :: "r"(ad),     "h"(hb));
                asm volatile("st.shared.u16 [%0], %1;" :: "r"(ad + 2), "h"(lb));
                asm volatile("st.shared.u16 [%0], %1;" :: "r"(ad + 4), "h"(hb));
            }
        }
        __syncwarp();

        // ---- O += P' V'  (k = 96 per warp-half) ----
#pragma unroll
        for (int ks2 = 0; ks2 < 6; ks2++) {
            uint32_t A[4];
            uint32_t aaddr = sP + (uint32_t)((wm * 16 + lrow + ((grp & 1) << 3)) * SP_STR
                                             + (wn * 96 + ks2 * 16 + ((grp >> 1) << 3)) * 2);
            LDSM_X4(A[0], A[1], A[2], A[3], aaddr);
#pragma unroll
            for (int ntp = 0; ntp < 8; ntp++) {
                uint32_t b0, b1, b2, b3;
                uint32_t baddr = sV + (uint32_t)((wn * 96 + ks2 * 16 + lrow + ((grp & 1) << 3)) * SV_STR
                                                 + (ntp * 16 + ((grp >> 1) << 3)) * 2);
                LDSM_X4_T(b0, b1, b2, b3, baddr);
                MMA_BF16(Oc[2 * ntp],     A, b0, b1);
                MMA_BF16(Oc[2 * ntp + 1], A, b2, b3);
            }
        }
    }

    // ---- merge the two t-halves ----
    __syncthreads();
    if (wn == 1) {
#pragma unroll
        for (int nt = 0; nt < 16; nt++) {
            int col = nt * 8 + 2 * (lane & 3);
            *(float2*)&mergeO[ra * 128 + col]       = make_float2(Oc[nt][0], Oc[nt][1]);
            *(float2*)&mergeO[(ra + 8) * 128 + col] = make_float2(Oc[nt][2], Oc[nt][3]);
        }
        if ((lane & 3) == 0) {
            mergeM[ra] = m0;     mergeM[ra + 8] = m1;
            mergeL[ra] = l0;     mergeL[ra + 8] = l1;
        }
    }
    __syncthreads();
    if (wn == 0) {
        float M1a = mergeM[ra],     L1a = mergeL[ra];
        float M1b = mergeM[ra + 8], L1b = mergeL[ra + 8];
        float Ma = fmaxf(m0, M1a);
        float w0a = __expf(m0 - Ma), w1a = __expf(M1a - Ma);
        float inva = 1.0f / (l0 * w0a + L1a * w1a);
        float Mb = fmaxf(m1, M1b);
        float w0b = __expf(m1 - Mb), w1b = __expf(M1b - Mb);
        float invb = 1.0f / (l1 * w0b + L1b * w1b);

        size_t obase = ((size_t)(b * SEQ + q0)) * DIM + h * HD;
#pragma unroll
        for (int nt = 0; nt < 16; nt++) {
            int col = nt * 8 + 2 * (lane & 3);
            float2 o1a = *(float2*)&mergeO[ra * 128 + col];
            float2 o1b = *(float2*)&mergeO[(ra + 8) * 128 + col];
            float2 oa = make_float2((Oc[nt][0] * w0a + o1a.x * w1a) * inva,
                                    (Oc[nt][1] * w0a + o1a.y * w1a) * inva);
            float2 ob = make_float2((Oc[nt][2] * w0b + o1b.x * w1b) * invb,
                                    (Oc[nt][3] * w0b + o1b.y * w1b) * invb);
            *(float2*)&Oout[obase + (size_t)ra * DIM + col]       = oa;
            *(float2*)&Oout[obase + (size_t)(ra + 8) * DIM + col] = ob;
        }
    }
}

// ---------------------------------------------------------------------------
extern "C" void kernel_launch(void* const* d_in, const int* in_sizes, int n_in,
                              void* d_out, int out_size)
{
    const float* x  = (const float*)d_in[0];
    const float* wq = (const float*)d_in[1];
    const float* wk = (const float*)d_in[2];
    const float* wv = (const float*)d_in[3];
    const float* wo = (const float*)d_in[4];
    const float* fc = (const float*)d_in[5];
    const float* fs = (const float*)d_in[6];
    float* out = (float*)d_out;

    float *qp, *kp, *vp, *ap;
    uint16_t *xs, *as, *wqs, *wks, *wvs, *wos, *qs2, *ks2, *vs2;
    cudaGetSymbolAddress((void**)&qp, g_q);
    cudaGetSymbolAddress((void**)&kp, g_k);
    cudaGetSymbolAddress((void**)&vp, g_v);
    cudaGetSymbolAddress((void**)&ap, g_attn);
    cudaGetSymbolAddress((void**)&xs, g_xs);
    cudaGetSymbolAddress((void**)&as, g_as);
    cudaGetSymbolAddress((void**)&wqs, g_wqs);
    cudaGetSymbolAddress((void**)&wks, g_wks);
    cudaGetSymbolAddress((void**)&wvs, g_wvs);
    cudaGetSymbolAddress((void**)&wos, g_wos);
    cudaGetSymbolAddress((void**)&qs2, g_qs2);
    cudaGetSymbolAddress((void**)&ks2, g_ks2);
    cudaGetSymbolAddress((void**)&vs2, g_vs2);

    cudaFuncSetAttribute(gemm_hmma, cudaFuncAttributeMaxDynamicSharedMemorySize, GSMEM);
    cudaFuncSetAttribute(attn_mma, cudaFuncAttributeMaxDynamicSharedMemorySize, ATT_SMEM);

    // Split inputs for projections
    {
        int t8_big = MROWS * DIM / 8;
        int t8_kv  = KVDIM * DIM / 8;
        split_kernel<1><<<t8_big / 256, 256>>>(x,  xs,  t8_big);
        split_kernel<0><<<t8_big / 256, 256>>>(wq, wqs, t8_big);
        split_kernel<0><<<t8_kv  / 256, 256>>>(wk, wks, t8_kv);
        split_kernel<0><<<t8_kv  / 256, 256>>>(wv, wvs, t8_kv);
        split_kernel<0><<<t8_big / 256, 256>>>(wo, wos, t8_big);
    }

    // QKV projections (HMMA)
    gemm_hmma<<<dim3(DIM   / 128, MROWS / 128), 256, GSMEM>>>(xs, wqs, qp, MROWS, DIM);
    gemm_hmma<<<dim3(KVDIM / 128, MROWS / 128), 256, GSMEM>>>(xs, wks, kp, MROWS, KVDIM);
    gemm_hmma<<<dim3(KVDIM / 128, MROWS / 128), 256, GSMEM>>>(xs, wvs, vp, MROWS, KVDIM);

    // RoPE + split for attention operands
    rope_split<1><<<(BATCH * NH  * SEQ * 16) / 256, 256>>>(qp, qs2, fc, fs);
    rope_split<0><<<(BATCH * NKV * SEQ * 16) / 256, 256>>>(kp, ks2, fc, fs);
    split_v_kernel<<<(BATCH * NKV * SEQ * 16) / 256, 256>>>(vp, vs2);

    // HMMA flash attention
    attn_mma<<<dim3(SEQ / 64, BATCH * NH), 256, ATT_SMEM>>>(qs2, ks2, vs2, ap);

    // Output projection
    split_kernel<1><<<(MROWS * DIM / 8) / 256, 256>>>(ap, as, MROWS * DIM / 8);
    gemm_hmma<<<dim3(DIM / 128, MROWS / 128), 256, GSMEM>>>(as, wos, out, MROWS, DIM);
}